// round 1
// baseline (speedup 1.0000x reference)
#include <cuda_runtime.h>
#include <cuda_bf16.h>
#include <cstdint>

#define S_DIM 128
#define N_DIM 256
#define CM    256
#define CH    32
#define CZ    128

// scratch: a,b projections [S][N][CH]
__device__ float g_a[S_DIM * N_DIM * CH];
__device__ float g_b[S_DIM * N_DIM * CH];

// ---------------------------------------------------------------------------
// Kernel A: LayerNorm over c_m + two projections (w1,w2) + mask, fused.
// One block = 8 rows (same s, consecutive n), 256 threads.
// ---------------------------------------------------------------------------
__global__ void __launch_bounds__(256) ln_proj_kernel(
    const float* __restrict__ m, const float* __restrict__ mask,
    const float* __restrict__ ln_w, const float* __restrict__ ln_b,
    const float* __restrict__ w1, const float* __restrict__ b1,
    const float* __restrict__ w2, const float* __restrict__ b2)
{
    __shared__ float lnsm[8][CM];
    __shared__ float pa[4][8][CH];
    __shared__ float pb[4][8][CH];
    __shared__ float masksm[8];

    int t    = threadIdx.x;
    int warp = t >> 5, lane = t & 31;
    int bid  = blockIdx.x;
    int s    = bid >> 5;            // 32 blocks per s  (N/8 = 32)
    int n0   = (bid & 31) << 3;

    // --- LayerNorm: warp r handles row (s, n0+r) ---
    {
        int r = warp;
        const float* row = m + ((size_t)s * N_DIM + n0 + r) * CM;
        float v[8];
        float sum = 0.f, sq = 0.f;
#pragma unroll
        for (int x = 0; x < 8; x++) {
            v[x] = row[lane + 32 * x];
            sum += v[x];
            sq  += v[x] * v[x];
        }
#pragma unroll
        for (int o = 16; o > 0; o >>= 1) {
            sum += __shfl_xor_sync(0xffffffffu, sum, o);
            sq  += __shfl_xor_sync(0xffffffffu, sq, o);
        }
        float mu  = sum * (1.f / CM);
        float var = sq * (1.f / CM) - mu * mu;
        float inv = rsqrtf(var + 1e-5f);
#pragma unroll
        for (int x = 0; x < 8; x++) {
            int k = lane + 32 * x;
            lnsm[r][k] = (v[x] - mu) * inv * ln_w[k] + ln_b[k];
        }
        if (lane == 0) masksm[r] = mask[s * N_DIM + n0 + r];
    }
    __syncthreads();

    // --- projections: warps 0-3 -> w1 (a), warps 4-7 -> w2 (b) ---
    {
        const float* W = (warp < 4) ? w1 : w2;
        int wq = warp & 3;                  // k-chunk [wq*64, wq*64+64)
        float acc[8];
#pragma unroll
        for (int r = 0; r < 8; r++) acc[r] = 0.f;
        int kbeg = wq * 64;
#pragma unroll 8
        for (int k = kbeg; k < kbeg + 64; k++) {
            float wv = W[k * CH + lane];    // coalesced across lanes
#pragma unroll
            for (int r = 0; r < 8; r++) acc[r] += lnsm[r][k] * wv;
        }
        if (warp < 4) {
#pragma unroll
            for (int r = 0; r < 8; r++) pa[wq][r][lane] = acc[r];
        } else {
#pragma unroll
            for (int r = 0; r < 8; r++) pb[wq][r][lane] = acc[r];
        }
    }
    __syncthreads();

    // --- combine partials, add bias, apply mask, store ---
    {
        int r = t >> 5, c = t & 31;
        float av = pa[0][r][c] + pa[1][r][c] + pa[2][r][c] + pa[3][r][c] + b1[c];
        float bv = pb[0][r][c] + pb[1][r][c] + pb[2][r][c] + pb[3][r][c] + b2[c];
        float mv = masksm[r];
        size_t off = ((size_t)s * N_DIM + n0 + r) * CH + c;
        g_a[off] = av * mv;
        g_b[off] = bv * mv;
    }
}

// ---------------------------------------------------------------------------
// Kernel B: per-CTA fused outer-product (P tile 128x128, K=S=128) + contraction
// with wo, + bo, / norm.  CTA = 4 i's x 4 j's = 16 (i,j) pairs. 256 threads.
// Dynamic smem: Psm[128][130] + union{As[8][128],Bs[8][128] | wosm[64][128]}
// ---------------------------------------------------------------------------
#define PSM_LD 130
#define SMEM_FLOATS (128 * PSM_LD + 64 * 128)

__global__ void __launch_bounds__(256) opm_kernel(
    const float* __restrict__ mask, const float* __restrict__ wo,
    const float* __restrict__ bo, float* __restrict__ out)
{
    extern __shared__ float smem[];
    float* Psm  = smem;                    // [128][130]
    float* rest = smem + 128 * PSM_LD;
    float* As   = rest;                    // [8][128] (phase 1)
    float* Bs   = rest + 8 * 128;          // [8][128] (phase 1)
    float* wosm = rest;                    // [64][128] (phase 2, reuses As/Bs)

    __shared__ float normsm[16];
    __shared__ float nparts[16][17];

    int t  = threadIdx.x;
    int i0 = blockIdx.x * 4, j0 = blockIdx.y * 4;
    int tx = t & 15, ty = t >> 4;

    // ---------------- phase 1: P[(ii,c)][(jj,d)] = sum_s a*b -------------
    float acc[8][8];
#pragma unroll
    for (int u = 0; u < 8; u++)
#pragma unroll
        for (int v = 0; v < 8; v++) acc[u][v] = 0.f;

    for (int kk = 0; kk < S_DIM; kk += 8) {
#pragma unroll
        for (int x = 0; x < 4; x++) {
            int idx = x * 256 + t;
            int sL = idx >> 7, r = idx & 127;
            As[idx] = g_a[(size_t)(kk + sL) * (N_DIM * CH) + i0 * CH + r];
            Bs[idx] = g_b[(size_t)(kk + sL) * (N_DIM * CH) + j0 * CH + r];
        }
        __syncthreads();
#pragma unroll
        for (int sL = 0; sL < 8; sL++) {
            float Ar[8], Br[8];
#pragma unroll
            for (int u = 0; u < 8; u++) {
                Ar[u] = As[sL * 128 + ty * 8 + u];
                Br[u] = Bs[sL * 128 + tx * 8 + u];
            }
#pragma unroll
            for (int u = 0; u < 8; u++)
#pragma unroll
                for (int v = 0; v < 8; v++) acc[u][v] += Ar[u] * Br[v];
        }
        __syncthreads();
    }

    // store P into smem
#pragma unroll
    for (int u = 0; u < 8; u++)
#pragma unroll
        for (int v = 0; v < 8; v++)
            Psm[(ty * 8 + u) * PSM_LD + tx * 8 + v] = acc[u][v];

    // norm[i,j] = sum_s mask[s,i]*mask[s,j] (+eps), 16 threads/pair
    {
        int p = t >> 4, sl = t & 15;
        int i = i0 + (p >> 2), j = j0 + (p & 3);
        float ns = 0.f;
        for (int s = sl; s < S_DIM; s += 16)
            ns += mask[s * N_DIM + i] * mask[s * N_DIM + j];
        nparts[p][sl] = ns;
    }
    __syncthreads();
    if (t < 16) {
        float ns = 0.f;
#pragma unroll
        for (int x = 0; x < 16; x++) ns += nparts[t][x];
        normsm[t] = ns + 1e-3f;
    }

    // ---------------- phase 2: OUT[p][z] = sum_cd P[p][cd] * wo[cd][z] ----
    // thread -> pairs {w, w+8}, z-quad = lane (z = lane*4 .. lane*4+3)
    int w = t >> 5, lane = t & 31;
    int rowA = ((w >> 2) * 32) * PSM_LD + (w & 3) * 32;        // pair w
    int rowB = (((w >> 2) + 2) * 32) * PSM_LD + (w & 3) * 32;  // pair w+8
    float4 a0 = {0.f, 0.f, 0.f, 0.f}, a1 = {0.f, 0.f, 0.f, 0.f};

    for (int cdc = 0; cdc < CH * CH; cdc += 64) {
        __syncthreads();     // previous wosm chunk fully consumed (also orders Psm/normsm)
#pragma unroll
        for (int x = 0; x < 32; x++) {
            int idx = x * 256 + t;
            wosm[idx] = wo[(size_t)cdc * CZ + idx];
        }
        __syncthreads();
#pragma unroll 8
        for (int cdL = 0; cdL < 64; cdL++) {
            int cd = cdc + cdL;
            int c = cd >> 5, d = cd & 31;
            float p0 = Psm[rowA + c * PSM_LD + d];   // broadcast within warp
            float p1 = Psm[rowB + c * PSM_LD + d];
            float4 wv = *(const float4*)&wosm[cdL * CZ + lane * 4];
            a0.x += p0 * wv.x; a0.y += p0 * wv.y; a0.z += p0 * wv.z; a0.w += p0 * wv.w;
            a1.x += p1 * wv.x; a1.y += p1 * wv.y; a1.z += p1 * wv.z; a1.w += p1 * wv.w;
        }
    }

    // epilogue: + bo, / norm, store
    float4 bv = *(const float4*)&bo[lane * 4];
    {
        int p = w;
        int i = i0 + (p >> 2), j = j0 + (p & 3);
        float inv = 1.f / normsm[p];
        float4 o;
        o.x = (a0.x + bv.x) * inv; o.y = (a0.y + bv.y) * inv;
        o.z = (a0.z + bv.z) * inv; o.w = (a0.w + bv.w) * inv;
        *(float4*)&out[((size_t)i * N_DIM + j) * CZ + lane * 4] = o;
    }
    {
        int p = w + 8;
        int i = i0 + (p >> 2), j = j0 + (p & 3);
        float inv = 1.f / normsm[p];
        float4 o;
        o.x = (a1.x + bv.x) * inv; o.y = (a1.y + bv.y) * inv;
        o.z = (a1.z + bv.z) * inv; o.w = (a1.w + bv.w) * inv;
        *(float4*)&out[((size_t)i * N_DIM + j) * CZ + lane * 4] = o;
    }
}

// ---------------------------------------------------------------------------
extern "C" void kernel_launch(void* const* d_in, const int* in_sizes, int n_in,
                              void* d_out, int out_size)
{
    const float* m    = (const float*)d_in[0];
    const float* mask = (const float*)d_in[1];
    const float* ln_w = (const float*)d_in[2];
    const float* ln_b = (const float*)d_in[3];
    const float* w1   = (const float*)d_in[4];
    const float* b1   = (const float*)d_in[5];
    const float* w2   = (const float*)d_in[6];
    const float* b2   = (const float*)d_in[7];
    const float* wo   = (const float*)d_in[8];
    const float* bo   = (const float*)d_in[9];
    float* out = (float*)d_out;

    (void)in_sizes; (void)n_in; (void)out_size;

    // Kernel A: 4096 blocks (128 s * 32 n-blocks), 256 threads
    ln_proj_kernel<<<S_DIM * (N_DIM / 8), 256>>>(m, mask, ln_w, ln_b, w1, b1, w2, b2);

    // Kernel B: 64x64 blocks, 256 threads, ~97KB dynamic smem
    static_assert(SMEM_FLOATS * 4 == 99328, "smem size");
    cudaFuncSetAttribute(opm_kernel, cudaFuncAttributeMaxDynamicSharedMemorySize,
                         SMEM_FLOATS * 4);
    dim3 gridB(N_DIM / 4, N_DIM / 4);
    opm_kernel<<<gridB, 256, SMEM_FLOATS * 4>>>(mask, wo, bo, out);
}

// round 3
// speedup vs baseline: 1.0023x; 1.0023x over previous
#include <cuda_runtime.h>
#include <cuda_bf16.h>
#include <cstdint>

#define S_DIM 128
#define N_DIM 256
#define CM    256
#define CH    32
#define CZ    128

// scratch: a,b projections [S][N][CH]
__device__ float g_a[S_DIM * N_DIM * CH];
__device__ float g_b[S_DIM * N_DIM * CH];

// ---------------------------------------------------------------------------
// Kernel A: LayerNorm over c_m + two projections (w1,w2) + mask, fused.
// One block = 8 rows (same s, consecutive n), 256 threads.
// ---------------------------------------------------------------------------
__global__ void __launch_bounds__(256) ln_proj_kernel(
    const float* __restrict__ m, const float* __restrict__ mask,
    const float* __restrict__ ln_w, const float* __restrict__ ln_b,
    const float* __restrict__ w1, const float* __restrict__ b1,
    const float* __restrict__ w2, const float* __restrict__ b2)
{
    __shared__ float lnsm[8][CM];
    __shared__ float pa[4][8][CH];
    __shared__ float pb[4][8][CH];
    __shared__ float masksm[8];

    int t    = threadIdx.x;
    int warp = t >> 5, lane = t & 31;
    int bid  = blockIdx.x;
    int s    = bid >> 5;            // 32 blocks per s  (N/8 = 32)
    int n0   = (bid & 31) << 3;

    // --- LayerNorm: warp r handles row (s, n0+r) ---
    {
        int r = warp;
        const float* row = m + ((size_t)s * N_DIM + n0 + r) * CM;
        float v[8];
        float sum = 0.f, sq = 0.f;
#pragma unroll
        for (int x = 0; x < 8; x++) {
            v[x] = row[lane + 32 * x];
            sum += v[x];
            sq  += v[x] * v[x];
        }
#pragma unroll
        for (int o = 16; o > 0; o >>= 1) {
            sum += __shfl_xor_sync(0xffffffffu, sum, o);
            sq  += __shfl_xor_sync(0xffffffffu, sq, o);
        }
        float mu  = sum * (1.f / CM);
        float var = sq * (1.f / CM) - mu * mu;
        float inv = rsqrtf(var + 1e-5f);
#pragma unroll
        for (int x = 0; x < 8; x++) {
            int k = lane + 32 * x;
            lnsm[r][k] = (v[x] - mu) * inv * ln_w[k] + ln_b[k];
        }
        if (lane == 0) masksm[r] = mask[s * N_DIM + n0 + r];
    }
    __syncthreads();

    // --- projections: warps 0-3 -> w1 (a), warps 4-7 -> w2 (b) ---
    {
        const float* W = (warp < 4) ? w1 : w2;
        int wq = warp & 3;                  // k-chunk [wq*64, wq*64+64)
        float acc[8];
#pragma unroll
        for (int r = 0; r < 8; r++) acc[r] = 0.f;
        int kbeg = wq * 64;
#pragma unroll 8
        for (int k = kbeg; k < kbeg + 64; k++) {
            float wv = W[k * CH + lane];    // coalesced across lanes
#pragma unroll
            for (int r = 0; r < 8; r++) acc[r] += lnsm[r][k] * wv;
        }
        if (warp < 4) {
#pragma unroll
            for (int r = 0; r < 8; r++) pa[wq][r][lane] = acc[r];
        } else {
#pragma unroll
            for (int r = 0; r < 8; r++) pb[wq][r][lane] = acc[r];
        }
    }
    __syncthreads();

    // --- combine partials, add bias, apply mask, store ---
    {
        int r = t >> 5, c = t & 31;
        float av = pa[0][r][c] + pa[1][r][c] + pa[2][r][c] + pa[3][r][c] + b1[c];
        float bv = pb[0][r][c] + pb[1][r][c] + pb[2][r][c] + pb[3][r][c] + b2[c];
        float mv = masksm[r];
        size_t off = ((size_t)s * N_DIM + n0 + r) * CH + c;
        g_a[off] = av * mv;
        g_b[off] = bv * mv;
    }
}

// ---------------------------------------------------------------------------
// Kernel B: per-CTA fused outer-product (P tile 128x128, K=S=128) + contraction
// with wo, + bo, / norm.  CTA = 4 i's x 4 j's = 16 (i,j) pairs. 256 threads.
// Dynamic smem: Psm[128][130] + union{As[8][128],Bs[8][128] | wosm[64][128]}
// ---------------------------------------------------------------------------
#define PSM_LD 130
#define SMEM_FLOATS (128 * PSM_LD + 64 * 128)

__global__ void __launch_bounds__(256) opm_kernel(
    const float* __restrict__ mask, const float* __restrict__ wo,
    const float* __restrict__ bo, float* __restrict__ out)
{
    extern __shared__ float smem[];
    float* Psm  = smem;                    // [128][130]
    float* rest = smem + 128 * PSM_LD;
    float* As   = rest;                    // [8][128] (phase 1)
    float* Bs   = rest + 8 * 128;          // [8][128] (phase 1)
    float* wosm = rest;                    // [64][128] (phase 2, reuses As/Bs)

    __shared__ float normsm[16];
    __shared__ float nparts[16][17];

    int t  = threadIdx.x;
    int i0 = blockIdx.x * 4, j0 = blockIdx.y * 4;
    int tx = t & 15, ty = t >> 4;

    // ---------------- phase 1: P[(ii,c)][(jj,d)] = sum_s a*b -------------
    float acc[8][8];
#pragma unroll
    for (int u = 0; u < 8; u++)
#pragma unroll
        for (int v = 0; v < 8; v++) acc[u][v] = 0.f;

    for (int kk = 0; kk < S_DIM; kk += 8) {
#pragma unroll
        for (int x = 0; x < 4; x++) {
            int idx = x * 256 + t;
            int sL = idx >> 7, r = idx & 127;
            As[idx] = g_a[(size_t)(kk + sL) * (N_DIM * CH) + i0 * CH + r];
            Bs[idx] = g_b[(size_t)(kk + sL) * (N_DIM * CH) + j0 * CH + r];
        }
        __syncthreads();
#pragma unroll
        for (int sL = 0; sL < 8; sL++) {
            float Ar[8], Br[8];
#pragma unroll
            for (int u = 0; u < 8; u++) {
                Ar[u] = As[sL * 128 + ty * 8 + u];
                Br[u] = Bs[sL * 128 + tx * 8 + u];
            }
#pragma unroll
            for (int u = 0; u < 8; u++)
#pragma unroll
                for (int v = 0; v < 8; v++) acc[u][v] += Ar[u] * Br[v];
        }
        __syncthreads();
    }

    // store P into smem
#pragma unroll
    for (int u = 0; u < 8; u++)
#pragma unroll
        for (int v = 0; v < 8; v++)
            Psm[(ty * 8 + u) * PSM_LD + tx * 8 + v] = acc[u][v];

    // norm[i,j] = sum_s mask[s,i]*mask[s,j] (+eps), 16 threads/pair
    {
        int p = t >> 4, sl = t & 15;
        int i = i0 + (p >> 2), j = j0 + (p & 3);
        float ns = 0.f;
        for (int s = sl; s < S_DIM; s += 16)
            ns += mask[s * N_DIM + i] * mask[s * N_DIM + j];
        nparts[p][sl] = ns;
    }
    __syncthreads();
    if (t < 16) {
        float ns = 0.f;
#pragma unroll
        for (int x = 0; x < 16; x++) ns += nparts[t][x];
        normsm[t] = ns + 1e-3f;
    }

    // ---------------- phase 2: OUT[p][z] = sum_cd P[p][cd] * wo[cd][z] ----
    // thread -> pairs {w, w+8}, z-quad = lane (z = lane*4 .. lane*4+3)
    int w = t >> 5, lane = t & 31;
    int rowA = ((w >> 2) * 32) * PSM_LD + (w & 3) * 32;        // pair w
    int rowB = (((w >> 2) + 2) * 32) * PSM_LD + (w & 3) * 32;  // pair w+8
    float4 a0 = {0.f, 0.f, 0.f, 0.f}, a1 = {0.f, 0.f, 0.f, 0.f};

    for (int cdc = 0; cdc < CH * CH; cdc += 64) {
        __syncthreads();     // previous wosm chunk fully consumed (also orders Psm/normsm)
#pragma unroll
        for (int x = 0; x < 32; x++) {
            int idx = x * 256 + t;
            wosm[idx] = wo[(size_t)cdc * CZ + idx];
        }
        __syncthreads();
#pragma unroll 8
        for (int cdL = 0; cdL < 64; cdL++) {
            int cd = cdc + cdL;
            int c = cd >> 5, d = cd & 31;
            float p0 = Psm[rowA + c * PSM_LD + d];   // broadcast within warp
            float p1 = Psm[rowB + c * PSM_LD + d];
            float4 wv = *(const float4*)&wosm[cdL * CZ + lane * 4];
            a0.x += p0 * wv.x; a0.y += p0 * wv.y; a0.z += p0 * wv.z; a0.w += p0 * wv.w;
            a1.x += p1 * wv.x; a1.y += p1 * wv.y; a1.z += p1 * wv.z; a1.w += p1 * wv.w;
        }
    }

    // epilogue: + bo, / norm, store
    float4 bv = *(const float4*)&bo[lane * 4];
    {
        int p = w;
        int i = i0 + (p >> 2), j = j0 + (p & 3);
        float inv = 1.f / normsm[p];
        float4 o;
        o.x = (a0.x + bv.x) * inv; o.y = (a0.y + bv.y) * inv;
        o.z = (a0.z + bv.z) * inv; o.w = (a0.w + bv.w) * inv;
        *(float4*)&out[((size_t)i * N_DIM + j) * CZ + lane * 4] = o;
    }
    {
        int p = w + 8;
        int i = i0 + (p >> 2), j = j0 + (p & 3);
        float inv = 1.f / normsm[p];
        float4 o;
        o.x = (a1.x + bv.x) * inv; o.y = (a1.y + bv.y) * inv;
        o.z = (a1.z + bv.z) * inv; o.w = (a1.w + bv.w) * inv;
        *(float4*)&out[((size_t)i * N_DIM + j) * CZ + lane * 4] = o;
    }
}

// ---------------------------------------------------------------------------
extern "C" void kernel_launch(void* const* d_in, const int* in_sizes, int n_in,
                              void* d_out, int out_size)
{
    const float* m    = (const float*)d_in[0];
    const float* mask = (const float*)d_in[1];
    const float* ln_w = (const float*)d_in[2];
    const float* ln_b = (const float*)d_in[3];
    const float* w1   = (const float*)d_in[4];
    const float* b1   = (const float*)d_in[5];
    const float* w2   = (const float*)d_in[6];
    const float* b2   = (const float*)d_in[7];
    const float* wo   = (const float*)d_in[8];
    const float* bo   = (const float*)d_in[9];
    float* out = (float*)d_out;

    (void)in_sizes; (void)n_in; (void)out_size;

    // Kernel A: 4096 blocks (128 s * 32 n-blocks), 256 threads
    ln_proj_kernel<<<S_DIM * (N_DIM / 8), 256>>>(m, mask, ln_w, ln_b, w1, b1, w2, b2);

    // Kernel B: 64x64 blocks, 256 threads, ~97KB dynamic smem
    static_assert(SMEM_FLOATS * 4 == 99328, "smem size");
    cudaFuncSetAttribute(opm_kernel, cudaFuncAttributeMaxDynamicSharedMemorySize,
                         SMEM_FLOATS * 4);
    dim3 gridB(N_DIM / 4, N_DIM / 4);
    opm_kernel<<<gridB, 256, SMEM_FLOATS * 4>>>(mask, wo, bo, out);
}

// round 7
// speedup vs baseline: 1.8188x; 1.8147x over previous
#include <cuda_runtime.h>
#include <cuda_bf16.h>
#include <cstdint>

#define S_DIM 128
#define N_DIM 256
#define CM    256
#define CH    32
#define CZ    128
#define KCD   (CH*CH)            // 1024
#define MPAIRS (N_DIM*N_DIM)     // 65536
#define NC    (N_DIM*CH)         // 8192

// ---------------- device scratch (allocation-free rule: __device__ globals) --
__device__ float g_a[S_DIM * NC];                       // [s][n*CH+c] fp32
__device__ float g_b[S_DIM * NC];
__device__ __align__(16) unsigned short g_ph[(size_t)MPAIRS * KCD]; // P hi bf16 [m][cd]
__device__ __align__(16) unsigned short g_pl[(size_t)MPAIRS * KCD]; // P lo bf16
__device__ __align__(16) unsigned short g_wth[CZ * KCD];            // woT hi bf16 [z][cd]
__device__ __align__(16) unsigned short g_wtl[CZ * KCD];            // woT lo bf16
__device__ float g_norm[MPAIRS];                        // norm + eps

// ---------------- helpers ---------------------------------------------------
__device__ __forceinline__ uint32_t smem_u32(const void* p) {
    uint32_t a;
    asm("{ .reg .u64 t; cvta.to.shared.u64 t, %1; cvt.u32.u64 %0, t; }"
        : "=r"(a) : "l"(p));
    return a;
}

__device__ __forceinline__ void split_bf16(float v, unsigned short& h, unsigned short& l) {
    __nv_bfloat16 hb = __float2bfloat16(v);
    __nv_bfloat16 lb = __float2bfloat16(v - __bfloat162float(hb));
    h = __bfloat16_as_ushort(hb);
    l = __bfloat16_as_ushort(lb);
}

__device__ __forceinline__ void ldsm_x4(uint32_t* r, uint32_t a) {
    asm volatile("ldmatrix.sync.aligned.m8n8.x4.shared.b16 {%0,%1,%2,%3}, [%4];"
        : "=r"(r[0]), "=r"(r[1]), "=r"(r[2]), "=r"(r[3]) : "r"(a));
}
__device__ __forceinline__ void ldsm_x4_t(uint32_t* r, uint32_t a) {
    asm volatile("ldmatrix.sync.aligned.m8n8.x4.trans.shared.b16 {%0,%1,%2,%3}, [%4];"
        : "=r"(r[0]), "=r"(r[1]), "=r"(r[2]), "=r"(r[3]) : "r"(a));
}
__device__ __forceinline__ void mma16816(float* c, const uint32_t* a, const uint32_t* b) {
    asm volatile("mma.sync.aligned.m16n8k16.row.col.f32.bf16.bf16.f32 "
        "{%0,%1,%2,%3}, {%4,%5,%6,%7}, {%8,%9}, {%0,%1,%2,%3};"
        : "+f"(c[0]), "+f"(c[1]), "+f"(c[2]), "+f"(c[3])
        : "r"(a[0]), "r"(a[1]), "r"(a[2]), "r"(a[3]), "r"(b[0]), "r"(b[1]));
}

// ---------------------------------------------------------------------------
// Kernel A: LayerNorm + two projections (unchanged from passing version)
// ---------------------------------------------------------------------------
__global__ void __launch_bounds__(256) ln_proj_kernel(
    const float* __restrict__ m, const float* __restrict__ mask,
    const float* __restrict__ ln_w, const float* __restrict__ ln_b,
    const float* __restrict__ w1, const float* __restrict__ b1,
    const float* __restrict__ w2, const float* __restrict__ b2)
{
    __shared__ float lnsm[8][CM];
    __shared__ float pa[4][8][CH];
    __shared__ float pb[4][8][CH];
    __shared__ float masksm[8];

    int t = threadIdx.x, warp = t >> 5, lane = t & 31;
    int bid = blockIdx.x;
    int s = bid >> 5, n0 = (bid & 31) << 3;

    {
        int r = warp;
        const float* row = m + ((size_t)s * N_DIM + n0 + r) * CM;
        float v[8], sum = 0.f, sq = 0.f;
#pragma unroll
        for (int x = 0; x < 8; x++) { v[x] = row[lane + 32 * x]; sum += v[x]; sq += v[x] * v[x]; }
#pragma unroll
        for (int o = 16; o > 0; o >>= 1) {
            sum += __shfl_xor_sync(0xffffffffu, sum, o);
            sq  += __shfl_xor_sync(0xffffffffu, sq, o);
        }
        float mu = sum * (1.f / CM);
        float inv = rsqrtf(sq * (1.f / CM) - mu * mu + 1e-5f);
#pragma unroll
        for (int x = 0; x < 8; x++) {
            int k = lane + 32 * x;
            lnsm[r][k] = (v[x] - mu) * inv * ln_w[k] + ln_b[k];
        }
        if (lane == 0) masksm[r] = mask[s * N_DIM + n0 + r];
    }
    __syncthreads();
    {
        const float* W = (warp < 4) ? w1 : w2;
        int wq = warp & 3;
        float acc[8];
#pragma unroll
        for (int r = 0; r < 8; r++) acc[r] = 0.f;
        int kbeg = wq * 64;
#pragma unroll 8
        for (int k = kbeg; k < kbeg + 64; k++) {
            float wv = W[k * CH + lane];
#pragma unroll
            for (int r = 0; r < 8; r++) acc[r] += lnsm[r][k] * wv;
        }
        if (warp < 4) {
#pragma unroll
            for (int r = 0; r < 8; r++) pa[wq][r][lane] = acc[r];
        } else {
#pragma unroll
            for (int r = 0; r < 8; r++) pb[wq][r][lane] = acc[r];
        }
    }
    __syncthreads();
    {
        int r = t >> 5, c = t & 31;
        float av = pa[0][r][c] + pa[1][r][c] + pa[2][r][c] + pa[3][r][c] + b1[c];
        float bv = pb[0][r][c] + pb[1][r][c] + pb[2][r][c] + pb[3][r][c] + b2[c];
        float mv = masksm[r];
        size_t off = ((size_t)s * N_DIM + n0 + r) * CH + c;
        g_a[off] = av * mv;
        g_b[off] = bv * mv;
    }
}

// woT: transpose + hi/lo split of wo  ([cd][z] -> [z][cd])
__global__ void __launch_bounds__(256) wot_kernel(const float* __restrict__ wo)
{
    int idx = blockIdx.x * 256 + threadIdx.x;        // 512 blocks -> 131072
    int z = idx >> 10, cd = idx & 1023;
    unsigned short h, l;
    split_bf16(wo[cd * CZ + z], h, l);
    g_wth[z * KCD + cd] = h;
    g_wtl[z * KCD + cd] = l;
}

// norm[i,j] = sum_s mask[s,i]*mask[s,j] + eps
__global__ void __launch_bounds__(256) norm_kernel(const float* __restrict__ mask)
{
    int i = blockIdx.x, j = threadIdx.x;
    float acc = 0.f;
#pragma unroll 8
    for (int s = 0; s < S_DIM; s++)
        acc += mask[s * N_DIM + i] * mask[s * N_DIM + j];
    g_norm[i * N_DIM + j] = acc + 1e-3f;
}

// ---------------------------------------------------------------------------
// GEMM1: P = a^T b  (M=N=8192, K=S=128) via mma.sync bf16, hi/lo 3-pass.
// smem layout: k-major [k][m] planes (transposed fill is conflict-free),
// fragments via ldmatrix.trans.  LDM1 = 136 elems (272 B) -> ldmatrix
// row stride 68 words = 4 banks, conflict-free.
// planes: A_H, A_L (from g_a, cols m0..), B_H, B_L (from g_b, cols n0..)
// ---------------------------------------------------------------------------
#define LDM1   136
#define LDM1B  (LDM1*2)
#define PL1    (64 * LDM1B)      // 17408 bytes per plane
#define SM1    (4 * PL1)         // 69632

__global__ void __launch_bounds__(256) gemm1_kernel()
{
    extern __shared__ unsigned char sm1[];
    unsigned short* Ah = (unsigned short*)(sm1);
    unsigned short* Al = (unsigned short*)(sm1 + PL1);
    unsigned short* Bh = (unsigned short*)(sm1 + 2 * PL1);
    unsigned short* Bl = (unsigned short*)(sm1 + 3 * PL1);
    const uint32_t sb = smem_u32(sm1);

    int t = threadIdx.x, w = t >> 5, lane = t & 31;
    int wm = w >> 1, wn = w & 1;
    int m0 = blockIdx.x * 128, n0 = blockIdx.y * 128;

    float C[2][8][4];
#pragma unroll
    for (int mi = 0; mi < 2; mi++)
#pragma unroll
        for (int ni = 0; ni < 8; ni++)
#pragma unroll
            for (int e = 0; e < 4; e++) C[mi][ni][e] = 0.f;

    int mloc = t & 127, sh = t >> 7;

    for (int ch = 0; ch < 2; ch++) {
        // ---- fill (transposed store: [k=s][m], conflict-free) ----
#pragma unroll 4
        for (int sp = 0; sp < 64; sp += 2) {
            int sl = sp + sh;
            int sg = ch * 64 + sl;
            float va = g_a[(size_t)sg * NC + m0 + mloc];
            float vb = g_b[(size_t)sg * NC + n0 + mloc];
            unsigned short h, l;
            split_bf16(va, h, l);
            Ah[sl * LDM1 + mloc] = h;  Al[sl * LDM1 + mloc] = l;
            split_bf16(vb, h, l);
            Bh[sl * LDM1 + mloc] = h;  Bl[sl * LDM1 + mloc] = l;
        }
        __syncthreads();

        // ---- compute: 3 passes x 4 ksteps x (2 mi x 8 ni) ----
#pragma unroll
        for (int pass = 0; pass < 3; pass++) {
            uint32_t Ab = sb + ((pass == 2) ? PL1 : 0);
            uint32_t Bb = sb + 2 * PL1 + ((pass == 1) ? PL1 : 0);
#pragma unroll
            for (int ks = 0; ks < 4; ks++) {
                int kb = ks * 16;
                uint32_t af[2][4];
#pragma unroll
                for (int mi = 0; mi < 2; mi++) {
                    int mb = wm * 32 + mi * 16;
                    uint32_t addr = Ab
                        + (uint32_t)(kb + ((lane >> 4) & 1) * 8 + (lane & 7)) * LDM1B
                        + (uint32_t)(mb + (lane & 8)) * 2;
                    ldsm_x4_t(af[mi], addr);
                }
                uint32_t bf[8][2];
#pragma unroll
                for (int np = 0; np < 4; np++) {       // ni pairs {2np, 2np+1}
                    int nb = wn * 64 + np * 16;
                    uint32_t addr = Bb
                        + (uint32_t)(kb + ((lane >> 3) & 1) * 8 + (lane & 7)) * LDM1B
                        + (uint32_t)(nb + (lane >> 4) * 8) * 2;
                    uint32_t r4[4];
                    ldsm_x4_t(r4, addr);
                    bf[2 * np][0] = r4[0]; bf[2 * np][1] = r4[1];
                    bf[2 * np + 1][0] = r4[2]; bf[2 * np + 1][1] = r4[3];
                }
#pragma unroll
                for (int mi = 0; mi < 2; mi++)
#pragma unroll
                    for (int ni = 0; ni < 8; ni++)
                        mma16816(C[mi][ni], af[mi], bf[ni]);
            }
        }
        __syncthreads();
    }

    // ---- epilogue: scatter hi/lo bf16 to g_ph/g_pl ----
    int gid = lane >> 2, ctid = lane & 3;
#pragma unroll
    for (int mi = 0; mi < 2; mi++) {
#pragma unroll
        for (int rr = 0; rr < 2; rr++) {
            int rg = m0 + wm * 32 + mi * 16 + gid + rr * 8;
            int i = rg >> 5, c = rg & 31;
#pragma unroll
            for (int ni = 0; ni < 8; ni++) {
                int ng = n0 + wn * 64 + ni * 8 + 2 * ctid;
                int j = ng >> 5, d = ng & 31;
                float v0 = C[mi][ni][rr * 2 + 0];
                float v1 = C[mi][ni][rr * 2 + 1];
                unsigned short h0, l0, h1, l1;
                split_bf16(v0, h0, l0);
                split_bf16(v1, h1, l1);
                size_t idx = ((size_t)(i * N_DIM + j)) * KCD + c * CH + d;
                *(uint32_t*)(g_ph + idx) = ((uint32_t)h1 << 16) | h0;
                *(uint32_t*)(g_pl + idx) = ((uint32_t)l1 << 16) | l0;
            }
        }
    }
}

// ---------------------------------------------------------------------------
// GEMM2: out = P @ wo  (M=65536, N=CZ=128, K=1024) via mma.sync bf16 3-pass.
// smem layout: natural [m][k] / [z][k], LDK2=72 elems (144 B: 16B-multiple for
// uint4 fills, 36-word stride -> conflict-free ldmatrix). 16 K-chunks of 64.
// ---------------------------------------------------------------------------
#define LDK2   72
#define LDK2B  (LDK2*2)
#define PL2    (128 * LDK2B)     // 18432 bytes per plane
#define SM2    (4 * PL2)         // 73728

__global__ void __launch_bounds__(256) gemm2_kernel(
    const float* __restrict__ bo, float* __restrict__ out)
{
    extern __shared__ unsigned char sm2[];
    const uint32_t sb = smem_u32(sm2);

    int t = threadIdx.x, w = t >> 5, lane = t & 31;
    int wm = w >> 1, wn = w & 1;
    int m0 = blockIdx.x * 128;

    float C[2][8][4];
#pragma unroll
    for (int mi = 0; mi < 2; mi++)
#pragma unroll
        for (int ni = 0; ni < 8; ni++)
#pragma unroll
            for (int e = 0; e < 4; e++) C[mi][ni][e] = 0.f;

    for (int ch = 0; ch < 16; ch++) {
        // ---- fill: 4 planes via uint4, fully coalesced, conflict-free ----
#pragma unroll
        for (int it = 0; it < 4; it++) {
            int vi = it * 256 + t;                 // 1024 vec8 per plane
            int r = vi >> 3, q = vi & 7;
            size_t ga = (size_t)(m0 + r) * KCD + ch * 64 + q * 8;
            size_t gb = (size_t)r * KCD + ch * 64 + q * 8;
            uint32_t dst = (uint32_t)(r * LDK2B + q * 16);
            *(uint4*)(sm2 + dst)           = *(const uint4*)(g_ph + ga);
            *(uint4*)(sm2 + PL2 + dst)     = *(const uint4*)(g_pl + ga);
            *(uint4*)(sm2 + 2 * PL2 + dst) = *(const uint4*)(g_wth + gb);
            *(uint4*)(sm2 + 3 * PL2 + dst) = *(const uint4*)(g_wtl + gb);
        }
        __syncthreads();

        // ---- compute ----
#pragma unroll
        for (int pass = 0; pass < 3; pass++) {
            uint32_t Ab = sb + ((pass == 2) ? PL2 : 0);
            uint32_t Bb = sb + 2 * PL2 + ((pass == 1) ? PL2 : 0);
#pragma unroll
            for (int ks = 0; ks < 4; ks++) {
                int kb = ks * 16;
                uint32_t af[2][4];
#pragma unroll
                for (int mi = 0; mi < 2; mi++) {
                    int mb = wm * 32 + mi * 16;
                    uint32_t addr = Ab
                        + (uint32_t)(mb + (lane & 15)) * LDK2B
                        + (uint32_t)(kb + (lane >> 4) * 8) * 2;
                    ldsm_x4(af[mi], addr);
                }
                uint32_t bf[8][2];
#pragma unroll
                for (int np = 0; np < 4; np++) {
                    int nb = wn * 64 + np * 16;
                    uint32_t addr = Bb
                        + (uint32_t)(nb + (lane >> 4) * 8 + (lane & 7)) * LDK2B
                        + (uint32_t)(kb + ((lane >> 3) & 1) * 8) * 2;
                    uint32_t r4[4];
                    ldsm_x4(r4, addr);
                    bf[2 * np][0] = r4[0]; bf[2 * np][1] = r4[1];
                    bf[2 * np + 1][0] = r4[2]; bf[2 * np + 1][1] = r4[3];
                }
#pragma unroll
                for (int mi = 0; mi < 2; mi++)
#pragma unroll
                    for (int ni = 0; ni < 8; ni++)
                        mma16816(C[mi][ni], af[mi], bf[ni]);
            }
        }
        __syncthreads();
    }

    // ---- epilogue: + bo, / norm, store float2 ----
    int gid = lane >> 2, ctid = lane & 3;
#pragma unroll
    for (int mi = 0; mi < 2; mi++) {
#pragma unroll
        for (int rr = 0; rr < 2; rr++) {
            int rg = m0 + wm * 32 + mi * 16 + gid + rr * 8;
            float inv = 1.f / g_norm[rg];
#pragma unroll
            for (int ni = 0; ni < 8; ni++) {
                int z = wn * 64 + ni * 8 + 2 * ctid;
                float2 o;
                o.x = (C[mi][ni][rr * 2 + 0] + bo[z])     * inv;
                o.y = (C[mi][ni][rr * 2 + 1] + bo[z + 1]) * inv;
                *(float2*)(out + (size_t)rg * CZ + z) = o;
            }
        }
    }
}

// ---------------------------------------------------------------------------
extern "C" void kernel_launch(void* const* d_in, const int* in_sizes, int n_in,
                              void* d_out, int out_size)
{
    const float* m    = (const float*)d_in[0];
    const float* mask = (const float*)d_in[1];
    const float* ln_w = (const float*)d_in[2];
    const float* ln_b = (const float*)d_in[3];
    const float* w1   = (const float*)d_in[4];
    const float* b1   = (const float*)d_in[5];
    const float* w2   = (const float*)d_in[6];
    const float* b2   = (const float*)d_in[7];
    const float* wo   = (const float*)d_in[8];
    const float* bo   = (const float*)d_in[9];
    float* out = (float*)d_out;
    (void)in_sizes; (void)n_in; (void)out_size;

    cudaFuncSetAttribute(gemm1_kernel, cudaFuncAttributeMaxDynamicSharedMemorySize, SM1);
    cudaFuncSetAttribute(gemm2_kernel, cudaFuncAttributeMaxDynamicSharedMemorySize, SM2);

    ln_proj_kernel<<<S_DIM * (N_DIM / 8), 256>>>(m, mask, ln_w, ln_b, w1, b1, w2, b2);
    wot_kernel<<<512, 256>>>(wo);
    norm_kernel<<<N_DIM, N_DIM>>>(mask);
    gemm1_kernel<<<dim3(64, 64), 256, SM1>>>();
    gemm2_kernel<<<512, 256, SM2>>>(bo, out);
}